// round 16
// baseline (speedup 1.0000x reference)
#include <cuda_runtime.h>
#include <cuda_bf16.h>
#include <math.h>
#include <stdint.h>

#define SEQ 2048
#define DMODEL 4096
#define NH 32
#define HD 128

// ===========================================================================
// PTX helpers (sm_103-safe subset)
// ===========================================================================
__device__ __forceinline__ uint32_t smem_u32(const void* p) {
    uint32_t a;
    asm("{ .reg .u64 t; cvta.to.shared.u64 t, %1; cvt.u32.u64 %0, t; }" : "=r"(a) : "l"(p));
    return a;
}
#define MBARRIER_INIT(addr, cnt) \
    asm volatile("mbarrier.init.shared.b64 [%0], %1;" :: "r"((uint32_t)(addr)), "r"((uint32_t)(cnt)) : "memory")
#define MBARRIER_EXPECT_TX(addr, bytes) \
    asm volatile("mbarrier.arrive.expect_tx.shared.b64 _, [%0], %1;" :: "r"((uint32_t)(addr)), "r"((uint32_t)(bytes)) : "memory")
#define MBARRIER_ARRIVE(addr) \
    asm volatile("mbarrier.arrive.shared.b64 _, [%0];" :: "r"((uint32_t)(addr)) : "memory")

#define MBARRIER_WAIT_PARITY(mbar_smem_addr, phase_parity) do { \
    uint32_t _mbar = (uint32_t)(mbar_smem_addr); \
    uint32_t _parity = (uint32_t)(phase_parity); \
    uint32_t _done; \
    asm volatile("{\n\t.reg .pred p;\n\t" \
        "mbarrier.try_wait.parity.acquire.cta.shared::cta.b64 p, [%1], %2;\n\t" \
        "selp.b32 %0, 1, 0, p;\n\t}" : "=r"(_done) : "r"(_mbar), "r"(_parity) : "memory"); \
    if (!_done) { \
        asm volatile("{\n\t.reg .pred P1;\n\t" \
            "WAIT_LOOP_%=:\n\t" \
            "mbarrier.try_wait.parity.acquire.cta.shared::cta.b64 P1, [%0], %1, 0x989680;\n\t" \
            "@P1 bra.uni WAIT_DONE_%=;\n\t" \
            "bra.uni WAIT_LOOP_%=;\n\t" \
            "WAIT_DONE_%=:\n\t}" :: "r"(_mbar), "r"(_parity) : "memory"); \
    } \
} while(0)

#define MBARRIER_WAIT_PARITY_RELAXED(mbar_smem_addr, phase_parity) do { \
    uint32_t _mbar = (uint32_t)(mbar_smem_addr); \
    uint32_t _parity = (uint32_t)(phase_parity); \
    uint32_t _done; \
    asm volatile("{\n\t.reg .pred p;\n\t" \
        "mbarrier.try_wait.parity.relaxed.cta.shared::cta.b64 p, [%1], %2, 0x989680;\n\t" \
        "selp.b32 %0, 1, 0, p;\n\t}" : "=r"(_done) : "r"(_mbar), "r"(_parity) : "memory"); \
    if (!_done) { \
        asm volatile("{\n\t.reg .pred P1;\n\t" \
            "WAIT_LOOP_%=:\n\t" \
            "mbarrier.try_wait.parity.relaxed.cta.shared::cta.b64 P1, [%0], %1, 0x989680;\n\t" \
            "@P1 bra.uni WAIT_DONE_%=;\n\t" \
            "bra.uni WAIT_LOOP_%=;\n\t" \
            "WAIT_DONE_%=:\n\t}" :: "r"(_mbar), "r"(_parity) : "memory"); \
    } \
} while(0)

__device__ __forceinline__ void bulk_g2s(uint32_t dst, const void* src,
                                         uint32_t bytes, uint32_t mbar) {
    asm volatile(
        "cp.async.bulk.shared::cluster.global.mbarrier::complete_tx::bytes [%0], [%1], %2, [%3];"
        :: "r"(dst), "l"(src), "r"(bytes), "r"(mbar) : "memory");
}

__device__ __forceinline__ void ldsm_x4(uint32_t addr, uint32_t& r0, uint32_t& r1,
                                        uint32_t& r2, uint32_t& r3) {
    asm volatile("ldmatrix.sync.aligned.m8n8.x4.shared.b16 {%0,%1,%2,%3}, [%4];"
        : "=r"(r0), "=r"(r1), "=r"(r2), "=r"(r3) : "r"(addr));
}

__device__ __forceinline__ void mma_bf16(float* c, uint32_t a0, uint32_t a1,
                                         uint32_t a2, uint32_t a3,
                                         uint32_t b0, uint32_t b1) {
    asm volatile(
        "mma.sync.aligned.m16n8k16.row.col.f32.bf16.bf16.f32 "
        "{%0,%1,%2,%3}, {%4,%5,%6,%7}, {%8,%9}, {%0,%1,%2,%3};"
        : "+f"(c[0]), "+f"(c[1]), "+f"(c[2]), "+f"(c[3])
        : "r"(a0), "r"(a1), "r"(a2), "r"(a3), "r"(b0), "r"(b1));
}

__device__ __forceinline__ float ex2f(float x) {
    float r;
    asm("ex2.approx.f32 %0, %1;" : "=f"(r) : "f"(x));
    return r;
}

// ===========================================================================
// Scratch (static device globals; no allocations anywhere)
// ===========================================================================
__device__ __align__(128) __nv_bfloat16 g_x2[(size_t)SEQ * 2 * DMODEL];
__device__ __align__(128) __nv_bfloat16 g_w1[(size_t)3 * DMODEL * 2 * DMODEL];
__device__ __align__(128) __nv_bfloat16 g_w2[(size_t)DMODEL * 2 * DMODEL];
__device__ __align__(128) __nv_bfloat16 g_q2[(size_t)NH * SEQ * 2 * HD];
__device__ __align__(128) __nv_bfloat16 g_k2[(size_t)NH * SEQ * 2 * HD];
__device__ __align__(128) __nv_bfloat16 g_vt[(size_t)NH * HD * 2 * SEQ];
__device__ __align__(128) __nv_bfloat16 g_c2[(size_t)SEQ * 2 * DMODEL];
__device__ float g_cos[SEQ * (HD / 2)];
__device__ float g_sin[SEQ * (HD / 2)];

// ===========================================================================
// Tiled/swizzled gmem layout: 128x64-bf16 tiles (16KB, SW128-swizzled)
// ===========================================================================
__device__ __forceinline__ size_t granule_off(int r, int k8, int ktiles) {
    int kt = k8 >> 3;
    uint32_t b = (uint32_t)((r & 127) * 128)
               + (((uint32_t)(k8 & 7) << 4) ^ ((uint32_t)(r & 7) << 4));
    return ((size_t)((r >> 7) * ktiles + kt) << 14) + b;
}

__device__ __forceinline__ void split8(const float* v, uint4& hi, uint4& lo) {
    uint32_t hw[4], lw[4];
    #pragma unroll
    for (int j = 0; j < 4; j++) {
        __nv_bfloat16 h0 = __float2bfloat16(v[2 * j]);
        __nv_bfloat16 h1 = __float2bfloat16(v[2 * j + 1]);
        __nv_bfloat16 l0 = __float2bfloat16(v[2 * j]     - __bfloat162float(h0));
        __nv_bfloat16 l1 = __float2bfloat16(v[2 * j + 1] - __bfloat162float(h1));
        hw[j] = (uint32_t)__bfloat16_as_ushort(h0) | ((uint32_t)__bfloat16_as_ushort(h1) << 16);
        lw[j] = (uint32_t)__bfloat16_as_ushort(l0) | ((uint32_t)__bfloat16_as_ushort(l1) << 16);
    }
    hi = make_uint4(hw[0], hw[1], hw[2], hw[3]);
    lo = make_uint4(lw[0], lw[1], lw[2], lw[3]);
}

__global__ __launch_bounds__(256)
void split_tiles_g(const float* __restrict__ in, __nv_bfloat16* __restrict__ out,
                   int R, int K, int ldin, long long izs, long long ozs)
{
    int z = blockIdx.y;
    long long idx = (long long)blockIdx.x * 256 + threadIdx.x;
    int kg = K / 8;
    long long tot = (long long)R * kg;
    if (idx >= tot) return;
    int r  = (int)(idx / kg);
    int k8 = (int)(idx - (long long)r * kg);
    const float* p = in + (long long)z * izs + (long long)r * ldin + k8 * 8;
    float v[8];
    float4 a = *(const float4*)p, b = *(const float4*)(p + 4);
    v[0]=a.x; v[1]=a.y; v[2]=a.z; v[3]=a.w; v[4]=b.x; v[5]=b.y; v[6]=b.z; v[7]=b.w;
    uint4 hi, lo; split8(v, hi, lo);
    char* o = (char*)(out + (long long)z * ozs);
    int ktiles = 2 * (K / 64);
    *(uint4*)(o + granule_off(r, k8, ktiles))          = hi;
    *(uint4*)(o + granule_off(r, k8 + K / 8, ktiles))  = lo;
}

__global__ __launch_bounds__(256)
void transpose_split_g(const float* __restrict__ in, __nv_bfloat16* __restrict__ out,
                       int K, int N, int ldin, long long izs, long long ozs)
{
    __shared__ float t[32][33];
    int z = blockIdx.z;
    const float* inz = in + (long long)z * izs;
    char* outz = (char*)(out + (long long)z * ozs);
    int n0 = blockIdx.x * 32, k0 = blockIdx.y * 32;
    int x = threadIdx.x, y = threadIdx.y;   // 32 x 8
    #pragma unroll
    for (int r = 0; r < 32; r += 8)
        t[y + r][x] = inz[(long long)(k0 + y + r) * ldin + n0 + x];
    __syncthreads();
    int tt = y * 32 + x;
    if (tt < 128) {
        int nn = tt >> 2, g = tt & 3;
        float v[8];
        #pragma unroll
        for (int j = 0; j < 8; j++) v[j] = t[g * 8 + j][nn];
        uint4 hi, lo; split8(v, hi, lo);
        int ktiles = 2 * (K / 64);
        int n = n0 + nn, k8 = (k0 >> 3) + g;
        *(uint4*)(outz + granule_off(n, k8, ktiles))         = hi;
        *(uint4*)(outz + granule_off(n, k8 + K / 8, ktiles)) = lo;
    }
}

// ===========================================================================
// RoPE table
// ===========================================================================
__global__ void build_rope_table()
{
    int idx = blockIdx.x * blockDim.x + threadIdx.x;
    if (idx >= SEQ * (HD / 2)) return;
    int i = idx % (HD / 2);
    int s = idx / (HD / 2);
    double freq_d = pow(10000.0, -(double)(2 * i) / (double)HD);
    float freq  = (float)freq_d;
    float angle = (float)s * freq;
    g_cos[idx] = (float)cos((double)angle);
    g_sin[idx] = (float)sin((double)angle);
}

// ===========================================================================
// mma.sync bf16 GEMM (3-term chunks over 2-term storage).
// BM=128, BN=128, BK=64; 128 threads (4 warps, 2x2, warp tile 64x64);
// 3-stage 32KB pipeline; 2 CTAs/SM.
// mode 0: plain fp32 C write. mode 1: fused QKV epilogue (ntb block = one
// head's q/k/v slice): rope+split -> g_q2/g_k2, transpose+split -> g_vt.
// ===========================================================================
#define GST 3
#define STAGE_BYTES 32768
#define GEMM_DYN_SMEM (GST * STAGE_BYTES + 1024)

__global__ __launch_bounds__(128, 2)
void gemm_mma(const __nv_bfloat16* __restrict__ A, const __nv_bfloat16* __restrict__ B,
              float* __restrict__ C, int nk0, int ldc, int mode)
{
    extern __shared__ char dyn[];
    __shared__ __align__(8) unsigned long long s_mbar[2 * GST];

    const int tid  = threadIdx.x;
    const int wid  = tid >> 5;
    const int lane = tid & 31;
    const int wm = wid >> 1, wn = wid & 1;
    const int mt = blockIdx.x, ntb = blockIdx.y;
    const int nk = 3 * nk0;

    uint32_t stages = (smem_u32(dyn) + 1023u) & ~1023u;
    uint32_t mb = smem_u32(s_mbar);

    if (tid == 0) {
        #pragma unroll
        for (int i = 0; i < GST; i++)  MBARRIER_INIT(mb + i * 8, 1);
        #pragma unroll
        for (int i = GST; i < 2 * GST; i++) MBARRIER_INIT(mb + i * 8, 4);
    }
    __syncthreads();

    const char* Ab = (const char*)A + (((size_t)mt * (2 * nk0)) << 14);
    const char* Bb = (const char*)B + (((size_t)ntb * (2 * nk0)) << 14);

    if (tid == 0) {
        for (int c = 0; c < GST - 1 && c < nk; c++) {
            int t = c / nk0, k = c % nk0;
            size_t ao = ((size_t)((t == 1 ? nk0 : 0) + k)) << 14;
            size_t bo = ((size_t)((t == 2 ? nk0 : 0) + k)) << 14;
            uint32_t st = stages + c * STAGE_BYTES;
            MBARRIER_EXPECT_TX(mb + c * 8, STAGE_BYTES);
            bulk_g2s(st,         Ab + ao, 16384, mb + c * 8);
            bulk_g2s(st + 16384, Bb + bo, 16384, mb + c * 8);
        }
    }

    const int r_a = wm * 64 + (lane & 15);
    const uint32_t a_rowoff = (uint32_t)r_a * 128;
    const uint32_t a_sw = (uint32_t)(r_a & 7) << 4;
    const uint32_t cbA  = (uint32_t)(lane >> 4) * 16;

    const int r_b = wn * 64 + (lane & 7) + ((lane >> 4) & 1) * 8;
    const uint32_t b_rowoff = 16384u + (uint32_t)r_b * 128;
    const uint32_t b_sw = (uint32_t)(r_b & 7) << 4;
    const uint32_t cbB  = (uint32_t)((lane >> 3) & 1) * 16;

    float acc[4][8][4];
    #pragma unroll
    for (int i = 0; i < 4; i++)
        #pragma unroll
        for (int j = 0; j < 8; j++)
            #pragma unroll
            for (int q = 0; q < 4; q++) acc[i][j][q] = 0.f;

    for (int c = 0; c < nk; c++) {
        if (tid == 0) {
            int jc = c + GST - 1;
            if (jc < nk) {
                int t = jc / nk0, k = jc % nk0;
                size_t ao = ((size_t)((t == 1 ? nk0 : 0) + k)) << 14;
                size_t bo = ((size_t)((t == 2 ? nk0 : 0) + k)) << 14;
                int s2 = jc % GST;
                if (jc >= GST)
                    MBARRIER_WAIT_PARITY_RELAXED(mb + (GST + s2) * 8, ((jc / GST) - 1) & 1);
                uint32_t st = stages + s2 * STAGE_BYTES;
                MBARRIER_EXPECT_TX(mb + s2 * 8, STAGE_BYTES);
                bulk_g2s(st,         Ab + ao, 16384, mb + s2 * 8);
                bulk_g2s(st + 16384, Bb + bo, 16384, mb + s2 * 8);
            }
        }

        int s = c % GST;
        MBARRIER_WAIT_PARITY(mb + s * 8, (c / GST) & 1);
        uint32_t st = stages + s * STAGE_BYTES;
        uint32_t abase = st + a_rowoff;
        uint32_t bbase = st + b_rowoff;

        #pragma unroll
        for (int kk = 0; kk < 4; kk++) {
            uint32_t a[4][4];
            uint32_t acol = a_sw ^ (cbA + kk * 32);
            #pragma unroll
            for (int mi = 0; mi < 4; mi++)
                ldsm_x4(abase + mi * 2048 + acol, a[mi][0], a[mi][1], a[mi][2], a[mi][3]);

            uint32_t b[8][2];
            uint32_t bcol = b_sw ^ (cbB + kk * 32);
            #pragma unroll
            for (int u = 0; u < 4; u++) {
                uint32_t r0, r1, r2, r3;
                ldsm_x4(bbase + u * 2048 + bcol, r0, r1, r2, r3);
                b[2 * u][0] = r0; b[2 * u][1] = r1;
                b[2 * u + 1][0] = r2; b[2 * u + 1][1] = r3;
            }

            #pragma unroll
            for (int mi = 0; mi < 4; mi++)
                #pragma unroll
                for (int nt = 0; nt < 8; nt++)
                    mma_bf16(acc[mi][nt], a[mi][0], a[mi][1], a[mi][2], a[mi][3],
                             b[nt][0], b[nt][1]);
        }

        if (lane == 0) MBARRIER_ARRIVE(mb + (GST + s) * 8);
    }

    if (mode == 0) {
        // plain fp32 epilogue
        const int row0 = mt * 128 + wm * 64;
        const int col0 = ntb * 128 + wn * 64;
        #pragma unroll
        for (int mi = 0; mi < 4; mi++) {
            int r = row0 + mi * 16 + (lane >> 2);
            #pragma unroll
            for (int nt = 0; nt < 8; nt++) {
                int cc = col0 + nt * 8 + (lane & 3) * 2;
                float2 v0 = { acc[mi][nt][0], acc[mi][nt][1] };
                float2 v1 = { acc[mi][nt][2], acc[mi][nt][3] };
                *(float2*)(C + (size_t)r * ldc + cc)       = v0;
                *(float2*)(C + (size_t)(r + 8) * ldc + cc) = v1;
            }
        }
        return;
    }

    // ---- fused QKV epilogue: region by ntb (0-31 q, 32-63 k, 64-95 v) ----
    const float SCALE = 0.08838834764831845f;
    float* stg = (float*)dyn;                // 128 x 132 fp32 = 67.6KB < 97KB
    int region = ntb >> 5;
    int head = ntb & 31;
    __syncthreads();                          // pipeline smem free now

    #pragma unroll
    for (int mi = 0; mi < 4; mi++) {
        int r = wm * 64 + mi * 16 + (lane >> 2);
        #pragma unroll
        for (int nt = 0; nt < 8; nt++) {
            int cc = wn * 64 + nt * 8 + (lane & 3) * 2;
            float x0 = acc[mi][nt][0], y0 = acc[mi][nt][1];
            float x1 = acc[mi][nt][2], y1 = acc[mi][nt][3];
            if (region < 2) {
                int i = cc >> 1;
                int s0 = mt * 128 + r, s1 = s0 + 8;
                float c0 = g_cos[s0 * 64 + i], sn0 = g_sin[s0 * 64 + i];
                float c1 = g_cos[s1 * 64 + i], sn1 = g_sin[s1 * 64 + i];
                float nx0 = x0 * c0 - y0 * sn0, ny0 = x0 * sn0 + y0 * c0;
                float nx1 = x1 * c1 - y1 * sn1, ny1 = x1 * sn1 + y1 * c1;
                if (region == 0) { nx0 *= SCALE; ny0 *= SCALE; nx1 *= SCALE; ny1 *= SCALE; }
                stg[r * 132 + cc]           = nx0;
                stg[r * 132 + cc + 1]       = ny0;
                stg[(r + 8) * 132 + cc]     = nx1;
                stg[(r + 8) * 132 + cc + 1] = ny1;
            } else {
                // transpose: stage [d][s]
                stg[cc * 132 + r]           = x0;
                stg[(cc + 1) * 132 + r]     = y0;
                stg[cc * 132 + r + 8]       = x1;
                stg[(cc + 1) * 132 + r + 8] = y1;
            }
        }
    }
    __syncthreads();

    char* outp;
    if (region == 0)      outp = (char*)g_q2 + (size_t)head * SEQ * 2 * HD * 2;
    else if (region == 1) outp = (char*)g_k2 + (size_t)head * SEQ * 2 * HD * 2;
    else                  outp = (char*)g_vt + (size_t)head * HD * 2 * SEQ * 2;

    #pragma unroll
    for (int it = 0; it < 16; it++) {
        int row = it * 8 + (tid >> 4);
        int g = tid & 15;
        float v[8];
        #pragma unroll
        for (int q = 0; q < 8; q++) v[q] = stg[row * 132 + g * 8 + q];
        uint4 hi, lo; split8(v, hi, lo);
        if (region < 2) {
            int s = mt * 128 + row;
            *(uint4*)(outp + granule_off(s, g, 4))      = hi;
            *(uint4*)(outp + granule_off(s, g + 16, 4)) = lo;
        } else {
            // row = d (0..127); k = s dimension
            *(uint4*)(outp + granule_off(row, mt * 16 + g, 64))       = hi;
            *(uint4*)(outp + granule_off(row, 256 + mt * 16 + g, 64)) = lo;
        }
    }
}

// ===========================================================================
// Flash attention: one CTA = (64 Q rows, head), 128 threads (4 warps).
// BN=64 K blocks, single-buffered K/V, 2 CTAs/SM. Epilogue writes g_c2
// tiled split directly (smem-staged granule assembly).
// smem: Q 32K | K 32K | V 32K
// ===========================================================================
#define FLASH_DYN_SMEM (3 * 32768 + 1024)

__global__ __launch_bounds__(128, 2)
void flash_attn(const __nv_bfloat16* __restrict__ q2,
                const __nv_bfloat16* __restrict__ k2,
                const __nv_bfloat16* __restrict__ vt)
{
    extern __shared__ char dyn[];
    __shared__ __align__(8) unsigned long long s_mbar[5];

    const int tid = threadIdx.x, wid = tid >> 5, lane = tid & 31;
    const int qb = blockIdx.x, h = blockIdx.y;
    const float L2E = 1.44269504f;

    uint32_t base = (smem_u32(dyn) + 1023u) & ~1023u;
    uint32_t Qs = base, Ks = base + 32768, Vs = base + 65536;
    uint32_t mb = smem_u32(s_mbar);

    if (tid == 0) {
        MBARRIER_INIT(mb + 0, 1);
        MBARRIER_INIT(mb + 8, 1);
        MBARRIER_INIT(mb + 16, 4);
        MBARRIER_INIT(mb + 24, 1);
        MBARRIER_INIT(mb + 32, 4);
    }
    __syncthreads();

    const char* Qg = (const char*)q2 + (size_t)h * SEQ * 2 * HD * 2
                   + (((size_t)(qb >> 1) * 4) << 14) + (size_t)(qb & 1) * 8192;
    const char* Kg = (const char*)k2 + (size_t)h * SEQ * 2 * HD * 2;
    const char* Vg = (const char*)vt + (size_t)h * HD * 2 * SEQ * 2;

    auto load_k = [&](int j) {
        size_t tr = ((size_t)(j >> 1) * 4) << 14;
        size_t half = (size_t)(j & 1) * 8192;
        MBARRIER_EXPECT_TX(mb + 8, 32768);
        #pragma unroll
        for (int kt = 0; kt < 4; kt++)
            bulk_g2s(Ks + kt * 8192, Kg + tr + ((size_t)kt << 14) + half, 8192, mb + 8);
    };
    auto load_v = [&](int j) {
        MBARRIER_EXPECT_TX(mb + 24, 32768);
        bulk_g2s(Vs,         Vg + ((size_t)j << 14),        16384, mb + 24);
        bulk_g2s(Vs + 16384, Vg + ((size_t)(32 + j) << 14), 16384, mb + 24);
    };

    if (tid == 0) {
        MBARRIER_EXPECT_TX(mb + 0, 32768);
        #pragma unroll
        for (int kt = 0; kt < 4; kt++)
            bulk_g2s(Qs + kt * 8192, Qg + ((size_t)kt << 14), 8192, mb + 0);
        load_k(0);
        load_v(0);
    }

    const int r_a = wid * 16 + (lane & 15);
    const uint32_t a_row = (uint32_t)r_a * 128;
    const uint32_t a_sw  = ((uint32_t)(r_a & 7)) << 4;
    const uint32_t a_kh  = ((uint32_t)(lane >> 4)) * 16;
    const int r_b = (lane & 7) + ((lane >> 4) & 1) * 8;
    const uint32_t b_sw = ((uint32_t)(r_b & 7)) << 4;
    const uint32_t b_kh = ((uint32_t)((lane >> 3) & 1)) * 16;

    float oacc[16][4];
    #pragma unroll
    for (int i = 0; i < 16; i++)
        #pragma unroll
        for (int q = 0; q < 4; q++) oacc[i][q] = 0.f;
    float m0 = -1e30f, m1 = -1e30f, l0 = 0.f, l1 = 0.f;

    MBARRIER_WAIT_PARITY(mb + 0, 0);

    for (int j = 0; j < 32; j++) {
        const int ph = j & 1;
        float sacc[8][4];
        #pragma unroll
        for (int i = 0; i < 8; i++)
            #pragma unroll
            for (int q = 0; q < 4; q++) sacc[i][q] = 0.f;

        MBARRIER_WAIT_PARITY(mb + 8, ph);

        #pragma unroll
        for (int t = 0; t < 3; t++) {
            uint32_t qtb = Qs + (t == 1 ? 16384 : 0);
            uint32_t ktb = Ks + (t == 2 ? 16384 : 0);
            #pragma unroll
            for (int kk = 0; kk < 8; kk++) {
                uint32_t a0, a1, a2, a3;
                ldsm_x4(qtb + (kk >> 2) * 8192 + a_row + (a_sw ^ (a_kh + (kk & 3) * 32)),
                        a0, a1, a2, a3);
                uint32_t kbb = ktb + (kk >> 2) * 8192;
                uint32_t kcol = b_sw ^ (b_kh + (kk & 3) * 32);
                #pragma unroll
                for (int u = 0; u < 4; u++) {
                    uint32_t b0, b1, b2, b3;
                    ldsm_x4(kbb + (uint32_t)(r_b + u * 16) * 128 + kcol, b0, b1, b2, b3);
                    mma_bf16(sacc[2 * u],     a0, a1, a2, a3, b0, b1);
                    mma_bf16(sacc[2 * u + 1], a0, a1, a2, a3, b2, b3);
                }
            }
        }

        if (lane == 0) MBARRIER_ARRIVE(mb + 16);
        if (tid == 0 && j + 1 < 32) {
            MBARRIER_WAIT_PARITY_RELAXED(mb + 16, ph);
            load_k(j + 1);
        }

        float rmax0 = -1e30f, rmax1 = -1e30f;
        #pragma unroll
        for (int i = 0; i < 8; i++) {
            rmax0 = fmaxf(rmax0, fmaxf(sacc[i][0], sacc[i][1]));
            rmax1 = fmaxf(rmax1, fmaxf(sacc[i][2], sacc[i][3]));
        }
        rmax0 = fmaxf(rmax0, __shfl_xor_sync(0xffffffffu, rmax0, 1));
        rmax0 = fmaxf(rmax0, __shfl_xor_sync(0xffffffffu, rmax0, 2));
        rmax1 = fmaxf(rmax1, __shfl_xor_sync(0xffffffffu, rmax1, 1));
        rmax1 = fmaxf(rmax1, __shfl_xor_sync(0xffffffffu, rmax1, 2));
        float mn0 = fmaxf(m0, rmax0), mn1 = fmaxf(m1, rmax1);
        float c0 = ex2f((m0 - mn0) * L2E), c1 = ex2f((m1 - mn1) * L2E);
        float rs0 = 0.f, rs1 = 0.f;
        #pragma unroll
        for (int i = 0; i < 8; i++) {
            float p0 = ex2f((sacc[i][0] - mn0) * L2E);
            float p1 = ex2f((sacc[i][1] - mn0) * L2E);
            float p2 = ex2f((sacc[i][2] - mn1) * L2E);
            float p3 = ex2f((sacc[i][3] - mn1) * L2E);
            sacc[i][0] = p0; sacc[i][1] = p1; sacc[i][2] = p2; sacc[i][3] = p3;
            rs0 += p0 + p1; rs1 += p2 + p3;
        }
        rs0 += __shfl_xor_sync(0xffffffffu, rs0, 1);
        rs0 += __shfl_xor_sync(0xffffffffu, rs0, 2);
        rs1 += __shfl_xor_sync(0xffffffffu, rs1, 1);
        rs1 += __shfl_xor_sync(0xffffffffu, rs1, 2);
        l0 = l0 * c0 + rs0;  l1 = l1 * c1 + rs1;
        m0 = mn0; m1 = mn1;
        #pragma unroll
        for (int i = 0; i < 16; i++) {
            oacc[i][0] *= c0; oacc[i][1] *= c0;
            oacc[i][2] *= c1; oacc[i][3] *= c1;
        }

        MBARRIER_WAIT_PARITY(mb + 24, ph);
        #pragma unroll
        for (int u = 0; u < 4; u++) {
            uint32_t phr[4], plr[4];
            {
                float e00 = sacc[2*u][0],   e01 = sacc[2*u][1];
                float e10 = sacc[2*u][2],   e11 = sacc[2*u][3];
                float e20 = sacc[2*u+1][0], e21 = sacc[2*u+1][1];
                float e30 = sacc[2*u+1][2], e31 = sacc[2*u+1][3];
                __nv_bfloat16 h00=__float2bfloat16(e00), h01=__float2bfloat16(e01);
                __nv_bfloat16 h10=__float2bfloat16(e10), h11=__float2bfloat16(e11);
                __nv_bfloat16 h20=__float2bfloat16(e20), h21=__float2bfloat16(e21);
                __nv_bfloat16 h30=__float2bfloat16(e30), h31=__float2bfloat16(e31);
                phr[0] = (uint32_t)__bfloat16_as_ushort(h00) | ((uint32_t)__bfloat16_as_ushort(h01) << 16);
                phr[1] = (uint32_t)__bfloat16_as_ushort(h10) | ((uint32_t)__bfloat16_as_ushort(h11) << 16);
                phr[2] = (uint32_t)__bfloat16_as_ushort(h20) | ((uint32_t)__bfloat16_as_ushort(h21) << 16);
                phr[3] = (uint32_t)__bfloat16_as_ushort(h30) | ((uint32_t)__bfloat16_as_ushort(h31) << 16);
                __nv_bfloat16 q00=__float2bfloat16(e00-__bfloat162float(h00));
                __nv_bfloat16 q01=__float2bfloat16(e01-__bfloat162float(h01));
                __nv_bfloat16 q10=__float2bfloat16(e10-__bfloat162float(h10));
                __nv_bfloat16 q11=__float2bfloat16(e11-__bfloat162float(h11));
                __nv_bfloat16 q20=__float2bfloat16(e20-__bfloat162float(h20));
                __nv_bfloat16 q21=__float2bfloat16(e21-__bfloat162float(h21));
                __nv_bfloat16 q30=__float2bfloat16(e30-__bfloat162float(h30));
                __nv_bfloat16 q31=__float2bfloat16(e31-__bfloat162float(h31));
                plr[0] = (uint32_t)__bfloat16_as_ushort(q00) | ((uint32_t)__bfloat16_as_ushort(q01) << 16);
                plr[1] = (uint32_t)__bfloat16_as_ushort(q10) | ((uint32_t)__bfloat16_as_ushort(q11) << 16);
                plr[2] = (uint32_t)__bfloat16_as_ushort(q20) | ((uint32_t)__bfloat16_as_ushort(q21) << 16);
                plr[3] = (uint32_t)__bfloat16_as_ushort(q30) | ((uint32_t)__bfloat16_as_ushort(q31) << 16);
            }
            uint32_t vhb = Vs;
            uint32_t vlb = Vs + 16384;
            uint32_t vcol = b_sw ^ (b_kh + u * 32);
            #pragma unroll
            for (int v = 0; v < 8; v++) {
                uint32_t roff = (uint32_t)(r_b + v * 16) * 128 + vcol;
                uint32_t b0, b1, b2, b3;
                ldsm_x4(vhb + roff, b0, b1, b2, b3);
                mma_bf16(oacc[2 * v],     phr[0], phr[1], phr[2], phr[3], b0, b1);
                mma_bf16(oacc[2 * v + 1], phr[0], phr[1], phr[2], phr[3], b2, b3);
                mma_bf16(oacc[2 * v],     plr[0], plr[1], plr[2], plr[3], b0, b1);
                mma_bf16(oacc[2 * v + 1], plr[0], plr[1], plr[2], plr[3], b2, b3);
                uint32_t c0r, c1r, c2r, c3r;
                ldsm_x4(vlb + roff, c0r, c1r, c2r, c3r);
                mma_bf16(oacc[2 * v],     phr[0], phr[1], phr[2], phr[3], c0r, c1r);
                mma_bf16(oacc[2 * v + 1], phr[0], phr[1], phr[2], phr[3], c2r, c3r);
            }
        }

        if (lane == 0) MBARRIER_ARRIVE(mb + 32);
        if (tid == 0 && j + 1 < 32) {
            MBARRIER_WAIT_PARITY_RELAXED(mb + 32, ph);
            load_v(j + 1);
        }
    }

    // ---- fused epilogue: O / l -> g_c2 tiled split (smem-staged) ----
    float i0 = 1.0f / l0, i1 = 1.0f / l1;
    float* stg = (float*)dyn;                // 64 x 132 fp32 = 33.8KB
    __syncthreads();                          // K/V/Q smem no longer needed
    {
        int r = wid * 16 + (lane >> 2);
        #pragma unroll
        for (int nt = 0; nt < 16; nt++) {
            int cc = nt * 8 + (lane & 3) * 2;
            stg[r * 132 + cc]           = oacc[nt][0] * i0;
            stg[r * 132 + cc + 1]       = oacc[nt][1] * i0;
            stg[(r + 8) * 132 + cc]     = oacc[nt][2] * i1;
            stg[(r + 8) * 132 + cc + 1] = oacc[nt][3] * i1;
        }
    }
    __syncthreads();
    char* co = (char*)g_c2;
    #pragma unroll
    for (int it = 0; it < 8; it++) {
        int row = it * 8 + (tid >> 4);
        int g = tid & 15;
        float v[8];
        #pragma unroll
        for (int q = 0; q < 8; q++) v[q] = stg[row * 132 + g * 8 + q];
        uint4 hi, lo; split8(v, hi, lo);
        int s = qb * 64 + row;
        *(uint4*)(co + granule_off(s, h * 16 + g, 128))       = hi;
        *(uint4*)(co + granule_off(s, 512 + h * 16 + g, 128)) = lo;
    }
}

// ===========================================================================
extern "C" void kernel_launch(void* const* d_in, const int* in_sizes, int n_in,
                              void* d_out, int out_size)
{
    const float* hidden = (const float*)d_in[0];   // [2048, 4096]
    const float* wqkv   = (const float*)d_in[1];   // [4096, 12288]
    const float* wo     = (const float*)d_in[2];   // [4096, 4096]
    float* out = (float*)d_out;                    // [2048, 4096]

    __nv_bfloat16 *x2, *w1, *w2, *q2, *k2, *vt, *c2;
    cudaGetSymbolAddress((void**)&x2, g_x2);
    cudaGetSymbolAddress((void**)&w1, g_w1);
    cudaGetSymbolAddress((void**)&w2, g_w2);
    cudaGetSymbolAddress((void**)&q2, g_q2);
    cudaGetSymbolAddress((void**)&k2, g_k2);
    cudaGetSymbolAddress((void**)&vt, g_vt);
    cudaGetSymbolAddress((void**)&c2, g_c2);

    cudaFuncSetAttribute(gemm_mma, cudaFuncAttributeMaxDynamicSharedMemorySize, GEMM_DYN_SMEM);
    cudaFuncSetAttribute(flash_attn, cudaFuncAttributeMaxDynamicSharedMemorySize, FLASH_DYN_SMEM);

    // ---- operand conversion ----
    split_tiles_g<<<dim3((2048 * 512 + 255) / 256, 1), 256>>>(
        hidden, x2, 2048, 4096, 4096, 0, 0);
    transpose_split_g<<<dim3(12288 / 32, 4096 / 32, 1), dim3(32, 8)>>>(
        wqkv, w1, 4096, 12288, 12288, 0, 0);
    transpose_split_g<<<dim3(4096 / 32, 4096 / 32, 1), dim3(32, 8)>>>(
        wo, w2, 4096, 4096, 4096, 0, 0);

    // ---- rope tables (consumed by QKV GEMM epilogue) ----
    build_rope_table<<<(SEQ * (HD / 2) + 255) / 256, 256>>>();

    // ---- QKV GEMM with fused rope/split/transpose epilogue ----
    gemm_mma<<<dim3(16, 96, 1), 128, GEMM_DYN_SMEM>>>(
        x2, w1, /*C=*/out /*unused*/, 64, 0, /*mode=*/1);

    // ---- fused flash attention (writes c2 tiled split directly) ----
    flash_attn<<<dim3(32, NH), 128, FLASH_DYN_SMEM>>>(q2, k2, vt);

    // ---- out = ctx @ Wo ----
    gemm_mma<<<dim3(16, 32, 1), 128, GEMM_DYN_SMEM>>>(
        c2, w2, out, 64, 4096, /*mode=*/0);
}